// round 1
// baseline (speedup 1.0000x reference)
#include <cuda_runtime.h>
#include <math_constants.h>

#define NTOK 1024
#define DIM 128
#define TI 8            // rows per block (kernel 2)
#define TJ 64           // j-tile
#define NT2 256         // threads, kernel 2
#define PITCH 129       // smem tile pitch (conflict-free both ways)
#define NTILE (NTOK / TJ)
#define LOG2E 1.4426950408889634f

// scratch for Q,K,V (static device arrays — no allocation)
__device__ float g_Q[NTOK * DIM];
__device__ float g_K[NTOK * DIM];
__device__ float g_V[NTOK * DIM];

// ---------------------------------------------------------------------------
// Kernel 1: Q,K,V = x @ W + b.  128 blocks x 384 threads, 8 rows per block,
// thread (d, mat) computes 8 output elements of one matrix.
// ---------------------------------------------------------------------------
__global__ __launch_bounds__(384) void qkv_kernel(
    const float* __restrict__ x,
    const float* __restrict__ WQ, const float* __restrict__ bQ,
    const float* __restrict__ WK, const float* __restrict__ bK,
    const float* __restrict__ WV, const float* __restrict__ bV)
{
    __shared__ float xs[8 * DIM];
    const int tid = threadIdx.x;
    const int i0 = blockIdx.x * 8;

    for (int idx = tid; idx < 8 * DIM; idx += 384)
        xs[idx] = x[i0 * DIM + idx];
    __syncthreads();

    const int d   = tid & 127;
    const int mat = tid >> 7;   // 0=Q 1=K 2=V
    const float* W = (mat == 0) ? WQ : (mat == 1) ? WK : WV;
    const float* b = (mat == 0) ? bQ : (mat == 1) ? bK : bV;
    float* outp    = (mat == 0) ? g_Q : (mat == 1) ? g_K : g_V;

    float acc[8];
    const float bv = b[d];
#pragma unroll
    for (int r = 0; r < 8; r++) acc[r] = bv;

    for (int k = 0; k < DIM; k += 4) {
        const float w0 = W[(k + 0) * DIM + d];
        const float w1 = W[(k + 1) * DIM + d];
        const float w2 = W[(k + 2) * DIM + d];
        const float w3 = W[(k + 3) * DIM + d];
#pragma unroll
        for (int r = 0; r < 8; r++) {
            const float4 xq = *(const float4*)&xs[r * DIM + k];
            acc[r] = fmaf(xq.x, w0, fmaf(xq.y, w1, fmaf(xq.z, w2, fmaf(xq.w, w3, acc[r]))));
        }
    }
#pragma unroll
    for (int r = 0; r < 8; r++)
        outp[(i0 + r) * DIM + d] = acc[r];
}

// ---------------------------------------------------------------------------
// Kernel 2: fused flash-style pass.
//   per row i: online softmax over j of e_ij = relu(Q_i+K_j).wA
//   accumulate R_i = sum_j p_ij relu(Q_i+K_j),  AV_i = sum_j p_ij V_j
//   epilogue:  out_i = AV_i/l + (R_i/l) @ W_Ev + b_Ev
// 128 blocks (8 rows each) x 256 threads. Dynamic smem ~78.4 KB.
// ---------------------------------------------------------------------------
__global__ __launch_bounds__(NT2) void attn_kernel(
    const float* __restrict__ wA,
    const float* __restrict__ W_Ev,
    const float* __restrict__ b_Ev,
    float* __restrict__ out)
{
    extern __shared__ float sm[];
    // layout (floats):
    float4* Qw4    = (float4*)sm;        // [DIM*4] float4 = 2048 floats: (Q[r0][d], Q[r0+4][d], wA[d], 0)
    float*  Ks     = sm + 2048;          // [TJ][PITCH] = 8256
    float*  Vs     = sm + 2048 + 8256;   // 8256
    float*  e_s    = sm + 18560;         // [8][TJ] = 512
    float*  p4s    = sm + 19072;         // [TJ][8] = 512 (16B-aligned rows)
    float*  scale_s= sm + 19584;         // [8]
    float*  l_s    = sm + 19592;         // [8]
    // total 19600 floats = 78400 B

    const int tid  = threadIdx.x;
    const int lane = tid & 31;
    const int warp = tid >> 5;           // reduce: warp w owns softmax row w
    const int je   = tid & 63;           // phase-e: j within tile
    const int r0   = tid >> 6;           // phase-e: rows r0 and r0+4
    const int d    = tid & 127;          // accum: feature dim
    const int h    = tid >> 7;           // accum: row group (rows 4h..4h+3)
    const int i0   = blockIdx.x * TI;

    // build packed Q/wA broadcast table
    for (int idx = tid; idx < DIM * 4; idx += NT2) {
        const int dd = idx >> 2, rr = idx & 3;
        Qw4[idx] = make_float4(g_Q[(i0 + rr) * DIM + dd],
                               g_Q[(i0 + rr + 4) * DIM + dd],
                               wA[dd], 0.f);
    }

    // accum-phase Q rows live in registers
    const float q0 = g_Q[(i0 + 4 * h + 0) * DIM + d];
    const float q1 = g_Q[(i0 + 4 * h + 1) * DIM + d];
    const float q2 = g_Q[(i0 + 4 * h + 2) * DIM + d];
    const float q3 = g_Q[(i0 + 4 * h + 3) * DIM + d];

    float af0 = 0.f, af1 = 0.f, af2 = 0.f, af3 = 0.f;  // relu-feature accum
    float av0 = 0.f, av1 = 0.f, av2 = 0.f, av3 = 0.f;  // V accum
    float m_w = -1e30f, l_w = 0.f;                     // row 'warp' softmax state

    for (int ti = 0; ti < NTILE; ti++) {
        const float* Kgt = g_K + ti * TJ * DIM;
        const float* Vgt = g_V + ti * TJ * DIM;
        __syncthreads();   // previous accum done (also covers Qw4 on first iter)
        for (int idx = tid; idx < TJ * DIM; idx += NT2) {
            const int j = idx >> 7, c = idx & 127;
            Ks[j * PITCH + c] = Kgt[idx];
            Vs[j * PITCH + c] = Vgt[idx];
        }
        __syncthreads();

        // ---- phase e: thread computes e for (r0, je) and (r0+4, je)
        float e0 = 0.f, e1 = 0.f;
        const float* kp = Ks + je * PITCH;
#pragma unroll 8
        for (int dd = 0; dd < DIM; dd++) {
            const float4 qw = Qw4[dd * 4 + r0];   // 16B broadcast
            const float  kv = kp[dd];             // conflict-free (pitch 129)
            e0 += fmaxf(qw.x + kv, 0.f) * qw.z;
            e1 += fmaxf(qw.y + kv, 0.f) * qw.z;
        }
        e_s[r0 * TJ + je]       = e0;
        e_s[(r0 + 4) * TJ + je] = e1;
        __syncthreads();

        // ---- online softmax: warp w reduces row w (64 values)
        {
            const float v1 = e_s[warp * TJ + lane];
            const float v2 = e_s[warp * TJ + 32 + lane];
            float mx = fmaxf(v1, v2);
#pragma unroll
            for (int off = 16; off; off >>= 1)
                mx = fmaxf(mx, __shfl_xor_sync(0xffffffffu, mx, off));
            const float m_new = fmaxf(m_w, mx);
            const float p1 = exp2f((v1 - m_new) * LOG2E);
            const float p2 = exp2f((v2 - m_new) * LOG2E);
            p4s[lane * 8 + warp]        = p1;
            p4s[(lane + 32) * 8 + warp] = p2;
            float s = p1 + p2;
#pragma unroll
            for (int off = 16; off; off >>= 1)
                s += __shfl_xor_sync(0xffffffffu, s, off);
            const float sc = exp2f((m_w - m_new) * LOG2E);
            l_w = l_w * sc + s;
            m_w = m_new;
            if (lane == 0) scale_s[warp] = sc;
        }
        __syncthreads();

        // ---- accumulate: thread owns dim d, rows 4h..4h+3
        const float4 sc4 = *(const float4*)&scale_s[h * 4];
        af0 *= sc4.x; av0 *= sc4.x;
        af1 *= sc4.y; av1 *= sc4.y;
        af2 *= sc4.z; av2 *= sc4.z;
        af3 *= sc4.w; av3 *= sc4.w;
#pragma unroll 4
        for (int j = 0; j < TJ; j++) {
            const float kv = Ks[j * PITCH + d];
            const float vv = Vs[j * PITCH + d];
            const float4 p = *(const float4*)&p4s[j * 8 + h * 4];  // 16B broadcast
            af0 += p.x * fmaxf(q0 + kv, 0.f); av0 += p.x * vv;
            af1 += p.y * fmaxf(q1 + kv, 0.f); av1 += p.y * vv;
            af2 += p.z * fmaxf(q2 + kv, 0.f); av2 += p.z * vv;
            af3 += p.w * fmaxf(q3 + kv, 0.f); av3 += p.w * vv;
        }
    }

    // publish softmax denominators
    if (lane == 0) l_s[warp] = l_w;
    __syncthreads();
    const float4 l4 = *(const float4*)&l_s[h * 4];
    const float il0 = 1.f / l4.x, il1 = 1.f / l4.y, il2 = 1.f / l4.z, il3 = 1.f / l4.w;

    // stash R (normalized relu-feature accum) packed as Rp[k][8], reuse Ks
    float* Rp = Ks;
    Rp[d * 8 + 4 * h + 0] = af0 * il0;
    Rp[d * 8 + 4 * h + 1] = af1 * il1;
    Rp[d * 8 + 4 * h + 2] = af2 * il2;
    Rp[d * 8 + 4 * h + 3] = af3 * il3;
    __syncthreads();

    // epilogue: out = AV/l + R @ W_Ev + b_Ev
    const float bv = b_Ev[d];
    float o0 = av0 * il0 + bv;
    float o1 = av1 * il1 + bv;
    float o2 = av2 * il2 + bv;
    float o3 = av3 * il3 + bv;
#pragma unroll 4
    for (int k = 0; k < DIM; k++) {
        const float wv = W_Ev[k * DIM + d];
        const float4 r4 = *(const float4*)&Rp[k * 8 + h * 4];
        o0 += r4.x * wv; o1 += r4.y * wv; o2 += r4.z * wv; o3 += r4.w * wv;
    }
    out[(i0 + 4 * h + 0) * DIM + d] = o0;
    out[(i0 + 4 * h + 1) * DIM + d] = o1;
    out[(i0 + 4 * h + 2) * DIM + d] = o2;
    out[(i0 + 4 * h + 3) * DIM + d] = o3;
}

// ---------------------------------------------------------------------------
extern "C" void kernel_launch(void* const* d_in, const int* in_sizes, int n_in,
                              void* d_out, int out_size)
{
    const float* x    = (const float*)d_in[0];
    const float* W_Q  = (const float*)d_in[1];
    const float* b_Q  = (const float*)d_in[2];
    const float* W_K  = (const float*)d_in[3];
    const float* b_K  = (const float*)d_in[4];
    const float* W_V  = (const float*)d_in[5];
    const float* b_V  = (const float*)d_in[6];
    const float* W_Ev = (const float*)d_in[7];
    const float* b_Ev = (const float*)d_in[8];
    const float* W_A  = (const float*)d_in[9];
    // d_in[10] = b_A: cancels in softmax, and sum(alpha)=1 handles b_Ev; unused.
    float* out = (float*)d_out;

    const int smem2 = 19600 * (int)sizeof(float);  // 78400 B
    cudaFuncSetAttribute(attn_kernel, cudaFuncAttributeMaxDynamicSharedMemorySize, smem2);

    qkv_kernel<<<NTOK / 8, 384>>>(x, W_Q, b_Q, W_K, b_K, W_V, b_V);
    attn_kernel<<<NTOK / TI, NT2, smem2>>>(W_A, W_Ev, b_Ev, out);
}